// round 8
// baseline (speedup 1.0000x reference)
#include <cuda_runtime.h>
#include <cuda_bf16.h>
#include <cstdint>

// GCN: 3 x (GEMM -> pull-mode normalized aggregate via CSR-by-dst) with ReLU.
// Shapes: N=100000 nodes, E=1600000 edges, D=64.
// CSR (counting sort by dst) is built once per launch and reused by all layers.
// Aggregate: one dst node per WARP (zero divergence), float2 slice per lane;
// edges processed in PAIRS so two independent 256B gathers are in flight.

#define DD 64
#define MAXN 100000
#define MAXE 1600000

// Scratch (static __device__ arrays: no allocation allowed)
__device__ float g_h[(size_t)MAXN * DD];   // GEMM output per layer
__device__ float g_a[(size_t)MAXN * DD];   // aggregation buffer (layers 1,2)
__device__ float g_dinv[MAXN];             // deg^{-1/2} (incl. self-loop)
__device__ int   g_cnt[MAXN];              // in-degree (real edges only)
__device__ int   g_off[MAXN];              // CSR row offsets (exclusive scan)
__device__ int   g_cur[MAXN];              // scatter cursors
__device__ int   g_bsum[512];              // per-block sums for scan
__device__ int   g_bexcl[512];             // exclusive-scanned block sums
__device__ int2  g_csr[MAXE];              // packed {src, norm-bits}, grouped by dst

// ---------------- CSR construction ----------------

__global__ void cnt_count_kernel(const int* __restrict__ dst, int* cnt, int nE) {
    int e = blockIdx.x * blockDim.x + threadIdx.x;
    if (e < nE) atomicAdd(&cnt[dst[e]], 1);
}

__global__ void dinv_kernel(const int* __restrict__ cnt, float* dinv, int n) {
    int i = blockIdx.x * blockDim.x + threadIdx.x;
    if (i < n) dinv[i] = rsqrtf((float)(cnt[i] + 1));   // +1 self-loop
}

// scan pass A: per-block sums of cnt
__global__ void scan_bsum_kernel(const int* __restrict__ cnt, int* bsum, int n) {
    __shared__ int s[256];
    int i = blockIdx.x * 256 + threadIdx.x;
    s[threadIdx.x] = (i < n) ? cnt[i] : 0;
    __syncthreads();
    for (int off = 128; off > 0; off >>= 1) {
        if (threadIdx.x < off) s[threadIdx.x] += s[threadIdx.x + off];
        __syncthreads();
    }
    if (threadIdx.x == 0) bsum[blockIdx.x] = s[0];
}

// scan pass B: exclusive scan of the block sums (nb <= 512, one block)
__global__ void scan_partials_kernel(const int* __restrict__ bsum, int* bexcl, int nb) {
    __shared__ int s[512];
    int t = threadIdx.x;
    int v = (t < nb) ? bsum[t] : 0;
    s[t] = v;
    __syncthreads();
    for (int off = 1; off < 512; off <<= 1) {
        int u = (t >= off) ? s[t - off] : 0;
        __syncthreads();
        s[t] += u;
        __syncthreads();
    }
    if (t < nb) bexcl[t] = s[t] - v;
}

// scan pass C: per-element exclusive offsets = bexcl[blk] + (incl - own)
__global__ void scan_final_kernel(const int* __restrict__ cnt,
                                  const int* __restrict__ bexcl,
                                  int* offs, int* cur, int n) {
    __shared__ int s[256];
    int i = blockIdx.x * 256 + threadIdx.x;
    int v = (i < n) ? cnt[i] : 0;
    s[threadIdx.x] = v;
    __syncthreads();
    for (int off = 1; off < 256; off <<= 1) {
        int u = (threadIdx.x >= off) ? s[threadIdx.x - off] : 0;
        __syncthreads();
        s[threadIdx.x] += u;
        __syncthreads();
    }
    if (i < n) {
        int o = bexcl[blockIdx.x] + s[threadIdx.x] - v;
        offs[i] = o;
        cur[i]  = o;
    }
}

// scatter edges into CSR slots; fold norm computation in; packed payload
__global__ void csr_fill_kernel(const int* __restrict__ src, const int* __restrict__ dst,
                                const float* __restrict__ dinv,
                                int* cur, int2* csr, int nE) {
    int e = blockIdx.x * blockDim.x + threadIdx.x;
    if (e >= nE) return;
    int s = src[e];
    int d = dst[e];
    int pos = atomicAdd(&cur[d], 1);
    float nrm = dinv[s] * dinv[d];
    csr[pos] = make_int2(s, __float_as_int(nrm));
}

// ---------------- GEMM: out_h[N,64] = act(in)[N,64] @ W[64,64] ----------------
// Block: 512 threads = 64 cols x 8 row-slots, 64 rows staged in smem.
// Each thread holds one W column in 64 registers; 8 output rows per thread.

template <bool RELU>
__global__ __launch_bounds__(512) void gemm_kernel(
    const float* __restrict__ in, const float* __restrict__ W,
    float* __restrict__ out_h, int n)
{
    __shared__ __align__(16) float ws[DD * DD];
    __shared__ __align__(16) float xs[64][DD];

    int tx = threadIdx.x & 63;   // output column
    int ty = threadIdx.x >> 6;   // row slot 0..7

    for (int i = threadIdx.x; i < DD * DD; i += 512) ws[i] = W[i];

    int row0 = blockIdx.x * 64;
    for (int i = threadIdx.x; i < 64 * (DD / 4); i += 512) {
        int lr = i >> 4;
        int c4 = i & 15;
        int r = row0 + lr;
        float4 v = make_float4(0.f, 0.f, 0.f, 0.f);
        if (r < n) {
            v = *reinterpret_cast<const float4*>(in + (size_t)r * DD + c4 * 4);
            if (RELU) {
                v.x = fmaxf(v.x, 0.f); v.y = fmaxf(v.y, 0.f);
                v.z = fmaxf(v.z, 0.f); v.w = fmaxf(v.w, 0.f);
            }
        }
        *reinterpret_cast<float4*>(&xs[lr][c4 * 4]) = v;
    }
    __syncthreads();

    float w[DD];
#pragma unroll
    for (int k = 0; k < DD; k++) w[k] = ws[k * DD + tx];

#pragma unroll
    for (int rr = 0; rr < 8; rr++) {
        int lr = ty + rr * 8;
        float acc = 0.f;
#pragma unroll
        for (int k4 = 0; k4 < DD / 4; k4++) {
            float4 xv = *reinterpret_cast<const float4*>(&xs[lr][k4 * 4]);
            acc = fmaf(xv.x, w[k4 * 4 + 0], acc);
            acc = fmaf(xv.y, w[k4 * 4 + 1], acc);
            acc = fmaf(xv.z, w[k4 * 4 + 2], acc);
            acc = fmaf(xv.w, w[k4 * 4 + 3], acc);
        }
        int grow = row0 + lr;
        if (grow < n) out_h[(size_t)grow * DD + tx] = acc;
    }
}

// ---------------- aggregate (pull): out[g] = b + h[g]*dinv[g]^2
//                                  + sum_{e: dst=g} h[src_e] * norm_e ----------------
// ONE dst node per warp: 32 lanes x float2 slice = 256B per row access.
// Edges processed in pairs: 2 payload loads -> 2 independent gathers -> FMAs,
// keeping MLP=2 on the L2-latency critical path. No intra-warp divergence.

__global__ __launch_bounds__(256) void aggregate_kernel(
    const float* __restrict__ h,
    const int* __restrict__ offs, const int* __restrict__ cnt,
    const int2* __restrict__ csr,
    const float* __restrict__ b, const float* __restrict__ dinv,
    float* __restrict__ out, int n)
{
    int g = blockIdx.x * 8 + (threadIdx.x >> 5);   // node = warp
    if (g >= n) return;
    int p = (threadIdx.x & 31) * 2;                // float2 slice per lane

    float di = dinv[g];
    float sc = di * di;
    float2 hv = *reinterpret_cast<const float2*>(h + (size_t)g * DD + p);
    float2 bv = *reinterpret_cast<const float2*>(b + p);
    float2 acc = make_float2(fmaf(hv.x, sc, bv.x), fmaf(hv.y, sc, bv.y));

    int start = offs[g];
    int len   = cnt[g];
    const int2* ep = csr + start;

    int i = 0;
    for (; i + 2 <= len; i += 2) {
        int2 e0 = __ldg(ep + i);
        int2 e1 = __ldg(ep + i + 1);
        // two independent gathers in flight
        float2 v0 = *reinterpret_cast<const float2*>(h + (size_t)e0.x * DD + p);
        float2 v1 = *reinterpret_cast<const float2*>(h + (size_t)e1.x * DD + p);
        float w0 = __int_as_float(e0.y);
        float w1 = __int_as_float(e1.y);
        acc.x = fmaf(v0.x, w0, acc.x);
        acc.y = fmaf(v0.y, w0, acc.y);
        acc.x = fmaf(v1.x, w1, acc.x);
        acc.y = fmaf(v1.y, w1, acc.y);
    }
    if (i < len) {
        int2 e0 = __ldg(ep + i);
        float w0 = __int_as_float(e0.y);
        float2 v0 = *reinterpret_cast<const float2*>(h + (size_t)e0.x * DD + p);
        acc.x = fmaf(v0.x, w0, acc.x);
        acc.y = fmaf(v0.y, w0, acc.y);
    }
    *reinterpret_cast<float2*>(out + (size_t)g * DD + p) = acc;
}

// ---------------- host launch ----------------

static inline int cdiv(long long a, int b) { return (int)((a + b - 1) / b); }

extern "C" void kernel_launch(void* const* d_in, const int* in_sizes, int n_in,
                              void* d_out, int out_size) {
    const float* x  = (const float*)d_in[0];
    const int*   ei = (const int*)  d_in[1];
    const float* W1 = (const float*)d_in[2];
    const float* b1 = (const float*)d_in[3];
    const float* W2 = (const float*)d_in[4];
    const float* b2 = (const float*)d_in[5];
    const float* W3 = (const float*)d_in[6];
    const float* b3 = (const float*)d_in[7];

    int n  = in_sizes[0] / DD;
    int nE = in_sizes[1] / 2;
    const int* src = ei;
    const int* dst = ei + nE;
    float* out = (float*)d_out;

    float *hbuf, *abuf, *dinv;
    int *cnt, *offs, *cur, *bsum, *bexcl;
    int2* csr;
    cudaGetSymbolAddress((void**)&hbuf,  g_h);
    cudaGetSymbolAddress((void**)&abuf,  g_a);
    cudaGetSymbolAddress((void**)&dinv,  g_dinv);
    cudaGetSymbolAddress((void**)&cnt,   g_cnt);
    cudaGetSymbolAddress((void**)&offs,  g_off);
    cudaGetSymbolAddress((void**)&cur,   g_cur);
    cudaGetSymbolAddress((void**)&bsum,  g_bsum);
    cudaGetSymbolAddress((void**)&bexcl, g_bexcl);
    cudaGetSymbolAddress((void**)&csr,   g_csr);

    int nblk = cdiv(n, 256);          // blocks over nodes
    int eblk = cdiv(nE, 256);         // blocks over edges

    // ---- build CSR by dst (once per launch, reused by all 3 layers) ----
    cudaMemsetAsync(cnt, 0, (size_t)n * sizeof(int));
    cnt_count_kernel<<<eblk, 256>>>(dst, cnt, nE);
    dinv_kernel<<<nblk, 256>>>(cnt, dinv, n);
    scan_bsum_kernel<<<nblk, 256>>>(cnt, bsum, n);
    scan_partials_kernel<<<1, 512>>>(bsum, bexcl, nblk);
    scan_final_kernel<<<nblk, 256>>>(cnt, bexcl, offs, cur, n);
    csr_fill_kernel<<<eblk, 256>>>(src, dst, dinv, cur, csr, nE);

    int gemm_blocks = cdiv(n, 64);
    int agg_blocks  = cdiv(n, 8);     // 8 warps = 8 nodes per block

    // Layer 1
    gemm_kernel<false><<<gemm_blocks, 512>>>(x, W1, hbuf, n);
    aggregate_kernel<<<agg_blocks, 256>>>(hbuf, offs, cnt, csr, b1, dinv, abuf, n);
    // Layer 2
    gemm_kernel<true><<<gemm_blocks, 512>>>(abuf, W2, hbuf, n);
    aggregate_kernel<<<agg_blocks, 256>>>(hbuf, offs, cnt, csr, b2, dinv, abuf, n);
    // Layer 3
    gemm_kernel<true><<<gemm_blocks, 512>>>(abuf, W3, hbuf, n);
    aggregate_kernel<<<agg_blocks, 256>>>(hbuf, offs, cnt, csr, b3, dinv, out, n);
}

// round 11
// speedup vs baseline: 1.1266x; 1.1266x over previous
#include <cuda_runtime.h>
#include <cuda_bf16.h>
#include <cstdint>

// GCN: 3 x (GEMM -> pull-mode normalized aggregate via CSR-by-dst) with ReLU.
// N=100000, E=1600000, D=64. CSR built once per launch, reused by all layers.
// GEMM: 4x8 register tiles, FFMA-bound (~24us floor). Aggregate: one node per
// warp, float2/lane, 4-8 edges in flight.

#define DD 64
#define MAXN 100000
#define MAXE 1600000

__device__ float g_h[(size_t)MAXN * DD];   // GEMM output per layer
__device__ float g_a[(size_t)MAXN * DD];   // aggregation buffer (layers 1,2)
__device__ float g_dinv[MAXN];             // deg^{-1/2} (incl. self-loop)
__device__ int   g_cnt[MAXN];              // in-degree (real edges only)
__device__ int   g_off[MAXN];              // CSR row offsets (exclusive scan)
__device__ int   g_cur[MAXN];              // scatter cursors
__device__ int   g_bsum[512];              // per-block sums for scan
__device__ int2  g_csr[MAXE];              // packed {src, norm-bits}, by dst

// ---------------- CSR construction ----------------

__global__ void cnt_count_kernel(const int* __restrict__ dst, int* cnt, int nE) {
    int e = blockIdx.x * blockDim.x + threadIdx.x;
    if (e < nE) atomicAdd(&cnt[dst[e]], 1);
}

// scan A: per-block sum of cnt -> bsum; also dinv = rsqrt(cnt+1)
__global__ void scanA_kernel(const int* __restrict__ cnt, int* bsum,
                             float* dinv, int n) {
    int i = blockIdx.x * 256 + threadIdx.x;
    int c = (i < n) ? cnt[i] : 0;
    if (i < n) dinv[i] = rsqrtf((float)(c + 1));
    for (int o = 16; o > 0; o >>= 1) c += __shfl_down_sync(0xFFFFFFFFu, c, o);
    __shared__ int wsum[8];
    if ((threadIdx.x & 31) == 0) wsum[threadIdx.x >> 5] = c;
    __syncthreads();
    if (threadIdx.x == 0) {
        int t = 0;
#pragma unroll
        for (int w = 0; w < 8; w++) t += wsum[w];
        bsum[blockIdx.x] = t;
    }
}

// scan B: block base = sum(bsum[0..bid)), local Hillis-Steele scan -> offs/cur
__global__ void scanB_kernel(const int* __restrict__ cnt, const int* __restrict__ bsum,
                             int* offs, int* cur, int n) {
    __shared__ int s[256];
    __shared__ int wsum[8];
    __shared__ int sbase;
    int bid = blockIdx.x, tid = threadIdx.x;

    int base = 0;
    for (int j = tid; j < bid; j += 256) base += bsum[j];
    for (int o = 16; o > 0; o >>= 1) base += __shfl_down_sync(0xFFFFFFFFu, base, o);
    if ((tid & 31) == 0) wsum[tid >> 5] = base;
    __syncthreads();
    if (tid == 0) {
        int t = 0;
#pragma unroll
        for (int w = 0; w < 8; w++) t += wsum[w];
        sbase = t;
    }
    __syncthreads();

    int i = bid * 256 + tid;
    int v = (i < n) ? cnt[i] : 0;
    s[tid] = v;
    __syncthreads();
    for (int o = 1; o < 256; o <<= 1) {
        int u = (tid >= o) ? s[tid - o] : 0;
        __syncthreads();
        s[tid] += u;
        __syncthreads();
    }
    if (i < n) {
        int o = sbase + s[tid] - v;
        offs[i] = o;
        cur[i]  = o;
    }
}

// scatter edges into CSR slots; fold norm computation in; packed payload
__global__ void csr_fill_kernel(const int* __restrict__ src, const int* __restrict__ dst,
                                const float* __restrict__ dinv,
                                int* cur, int2* csr, int nE) {
    int e = blockIdx.x * blockDim.x + threadIdx.x;
    if (e >= nE) return;
    int s = src[e];
    int d = dst[e];
    int pos = atomicAdd(&cur[d], 1);
    float nrm = dinv[s] * dinv[d];
    csr[pos] = make_int2(s, __float_as_int(nrm));
}

// ---------------- GEMM: out_h[N,64] = act(in)[N,64] @ W[64,64] ----------------
// Block 256 threads -> 128 rows x 64 cols. Thread tile: 4 rows (stride 32) x
// 8 cols. Per k: 4 conflict-free LDS.32 (x) + 2 broadcast LDS.128 (w) feed
// 32 FFMA -> FFMA-pipe bound (~24us/GEMM chip floor).

template <bool RELU>
__global__ __launch_bounds__(256) void gemm_kernel(
    const float* __restrict__ in, const float* __restrict__ W,
    float* __restrict__ out_h, int n)
{
    __shared__ __align__(16) float ws[DD][DD];      // ws[k][c]
    __shared__ __align__(16) float xs[128][DD + 4]; // +4 pad: conflict-free LDS

    int tid = threadIdx.x;
    int cg  = tid & 7;          // col group: 8 cols
    int rb  = tid >> 3;         // row base: rows rb + {0,32,64,96}
    int col0 = cg * 8;

    for (int i = tid; i < DD * (DD / 4); i += 256) {
        int k = i >> 4, c4 = i & 15;
        *reinterpret_cast<float4*>(&ws[k][c4 * 4]) =
            *reinterpret_cast<const float4*>(W + k * DD + c4 * 4);
    }

    int row0 = blockIdx.x * 128;
    for (int i = tid; i < 128 * (DD / 4); i += 256) {
        int lr = i >> 4, c4 = i & 15;
        int r = row0 + lr;
        float4 v = make_float4(0.f, 0.f, 0.f, 0.f);
        if (r < n) {
            v = *reinterpret_cast<const float4*>(in + (size_t)r * DD + c4 * 4);
            if (RELU) {
                v.x = fmaxf(v.x, 0.f); v.y = fmaxf(v.y, 0.f);
                v.z = fmaxf(v.z, 0.f); v.w = fmaxf(v.w, 0.f);
            }
        }
        *reinterpret_cast<float4*>(&xs[lr][c4 * 4]) = v;
    }
    __syncthreads();

    float acc[4][8];
#pragma unroll
    for (int j = 0; j < 4; j++)
#pragma unroll
        for (int c = 0; c < 8; c++) acc[j][c] = 0.f;

#pragma unroll 4
    for (int k = 0; k < DD; k++) {
        float x0 = xs[rb      ][k];
        float x1 = xs[rb + 32 ][k];
        float x2 = xs[rb + 64 ][k];
        float x3 = xs[rb + 96 ][k];
        float4 wa = *reinterpret_cast<const float4*>(&ws[k][col0]);
        float4 wb = *reinterpret_cast<const float4*>(&ws[k][col0 + 4]);
        float wv[8] = {wa.x, wa.y, wa.z, wa.w, wb.x, wb.y, wb.z, wb.w};
#pragma unroll
        for (int c = 0; c < 8; c++) {
            acc[0][c] = fmaf(x0, wv[c], acc[0][c]);
            acc[1][c] = fmaf(x1, wv[c], acc[1][c]);
            acc[2][c] = fmaf(x2, wv[c], acc[2][c]);
            acc[3][c] = fmaf(x3, wv[c], acc[3][c]);
        }
    }

#pragma unroll
    for (int j = 0; j < 4; j++) {
        int grow = row0 + rb + j * 32;
        if (grow < n) {
            *reinterpret_cast<float4*>(out_h + (size_t)grow * DD + col0) =
                make_float4(acc[j][0], acc[j][1], acc[j][2], acc[j][3]);
            *reinterpret_cast<float4*>(out_h + (size_t)grow * DD + col0 + 4) =
                make_float4(acc[j][4], acc[j][5], acc[j][6], acc[j][7]);
        }
    }
}

// ---------------- aggregate (pull): out[g] = b + h[g]*dinv[g]^2
//                                  + sum_{e: dst=g} h[src_e] * norm_e ----------------
// ONE dst node per warp: 32 lanes x float2 slice = 256B per row access.
// Edges processed 4 at a time (x2 unroll -> up to 8 gathers in flight).
// No intra-warp divergence (len is warp-uniform). Each row written once.

__global__ __launch_bounds__(256) void aggregate_kernel(
    const float* __restrict__ h,
    const int* __restrict__ offs, const int* __restrict__ cnt,
    const int2* __restrict__ csr,
    const float* __restrict__ b, const float* __restrict__ dinv,
    float* __restrict__ out, int n)
{
    int g = blockIdx.x * 8 + (threadIdx.x >> 5);   // node = warp
    if (g >= n) return;
    int p = (threadIdx.x & 31) * 2;                // float2 slice per lane

    float di = dinv[g];
    float sc = di * di;
    float2 hv = *reinterpret_cast<const float2*>(h + (size_t)g * DD + p);
    float2 bv = *reinterpret_cast<const float2*>(b + p);
    float2 acc = make_float2(fmaf(hv.x, sc, bv.x), fmaf(hv.y, sc, bv.y));

    int start = offs[g];
    int len   = cnt[g];
    const int2* ep = csr + start;

    int i = 0;
#pragma unroll 2
    for (; i + 4 <= len; i += 4) {
        int2 e0 = __ldg(ep + i);
        int2 e1 = __ldg(ep + i + 1);
        int2 e2 = __ldg(ep + i + 2);
        int2 e3 = __ldg(ep + i + 3);
        float2 v0 = *reinterpret_cast<const float2*>(h + (size_t)e0.x * DD + p);
        float2 v1 = *reinterpret_cast<const float2*>(h + (size_t)e1.x * DD + p);
        float2 v2 = *reinterpret_cast<const float2*>(h + (size_t)e2.x * DD + p);
        float2 v3 = *reinterpret_cast<const float2*>(h + (size_t)e3.x * DD + p);
        float w0 = __int_as_float(e0.y), w1 = __int_as_float(e1.y);
        float w2 = __int_as_float(e2.y), w3 = __int_as_float(e3.y);
        acc.x = fmaf(v0.x, w0, acc.x);  acc.y = fmaf(v0.y, w0, acc.y);
        acc.x = fmaf(v1.x, w1, acc.x);  acc.y = fmaf(v1.y, w1, acc.y);
        acc.x = fmaf(v2.x, w2, acc.x);  acc.y = fmaf(v2.y, w2, acc.y);
        acc.x = fmaf(v3.x, w3, acc.x);  acc.y = fmaf(v3.y, w3, acc.y);
    }
    for (; i < len; i++) {
        int2 e0 = __ldg(ep + i);
        float w0 = __int_as_float(e0.y);
        float2 v0 = *reinterpret_cast<const float2*>(h + (size_t)e0.x * DD + p);
        acc.x = fmaf(v0.x, w0, acc.x);
        acc.y = fmaf(v0.y, w0, acc.y);
    }
    *reinterpret_cast<float2*>(out + (size_t)g * DD + p) = acc;
}

// ---------------- host launch ----------------

static inline int cdiv(long long a, int b) { return (int)((a + b - 1) / b); }

extern "C" void kernel_launch(void* const* d_in, const int* in_sizes, int n_in,
                              void* d_out, int out_size) {
    const float* x  = (const float*)d_in[0];
    const int*   ei = (const int*)  d_in[1];
    const float* W1 = (const float*)d_in[2];
    const float* b1 = (const float*)d_in[3];
    const float* W2 = (const float*)d_in[4];
    const float* b2 = (const float*)d_in[5];
    const float* W3 = (const float*)d_in[6];
    const float* b3 = (const float*)d_in[7];

    int n  = in_sizes[0] / DD;
    int nE = in_sizes[1] / 2;
    const int* src = ei;
    const int* dst = ei + nE;
    float* out = (float*)d_out;

    float *hbuf, *abuf, *dinv;
    int *cnt, *offs, *cur, *bsum;
    int2* csr;
    cudaGetSymbolAddress((void**)&hbuf, g_h);
    cudaGetSymbolAddress((void**)&abuf, g_a);
    cudaGetSymbolAddress((void**)&dinv, g_dinv);
    cudaGetSymbolAddress((void**)&cnt,  g_cnt);
    cudaGetSymbolAddress((void**)&offs, g_off);
    cudaGetSymbolAddress((void**)&cur,  g_cur);
    cudaGetSymbolAddress((void**)&bsum, g_bsum);
    cudaGetSymbolAddress((void**)&csr,  g_csr);

    int nblk = cdiv(n, 256);
    int eblk = cdiv(nE, 256);
    int gemm_blocks = cdiv(n, 128);
    int agg_blocks  = cdiv(n, 8);

    // layer-1 GEMM is independent of the CSR build -> launch first
    cudaMemsetAsync(cnt, 0, (size_t)n * sizeof(int));
    gemm_kernel<false><<<gemm_blocks, 256>>>(x, W1, hbuf, n);

    // ---- build CSR by dst (once per launch, reused by all 3 layers) ----
    cnt_count_kernel<<<eblk, 256>>>(dst, cnt, nE);
    scanA_kernel<<<nblk, 256>>>(cnt, bsum, dinv, n);
    scanB_kernel<<<nblk, 256>>>(cnt, bsum, offs, cur, n);
    csr_fill_kernel<<<eblk, 256>>>(src, dst, dinv, cur, csr, nE);

    // Layer 1 aggregate
    aggregate_kernel<<<agg_blocks, 256>>>(hbuf, offs, cnt, csr, b1, dinv, abuf, n);
    // Layer 2
    gemm_kernel<true><<<gemm_blocks, 256>>>(abuf, W2, hbuf, n);
    aggregate_kernel<<<agg_blocks, 256>>>(hbuf, offs, cnt, csr, b2, dinv, abuf, n);
    // Layer 3
    gemm_kernel<true><<<gemm_blocks, 256>>>(abuf, W3, hbuf, n);
    aggregate_kernel<<<agg_blocks, 256>>>(hbuf, offs, cnt, csr, b3, dinv, out, n);
}

// round 12
// speedup vs baseline: 1.1775x; 1.0452x over previous
#include <cuda_runtime.h>
#include <cuda_fp16.h>
#include <cstdint>

// GCN: 3 x (GEMM -> pull-mode normalized aggregate via CSR-by-dst) with ReLU.
// N=100000, E=1600000, D=64. CSR built once per launch, reused by all layers.
// h (GEMM output) is stored FP16: it is consumed only by the aggregate's
// gathers, halving the dominant L2 gather traffic. All accumulation and the
// layer outputs (abuf / d_out) stay FP32.

#define DD 64
#define MAXN 100000
#define MAXE 1600000

__device__ __align__(16) unsigned short g_h16[(size_t)MAXN * DD]; // h in fp16
__device__ float g_a[(size_t)MAXN * DD];   // aggregation buffer (layers 1,2)
__device__ float g_dinv[MAXN];             // deg^{-1/2} (incl. self-loop)
__device__ int   g_cnt[MAXN];              // in-degree (real edges only)
__device__ int   g_off[MAXN];              // CSR row offsets (exclusive scan)
__device__ int   g_cur[MAXN];              // scatter cursors
__device__ int   g_bsum[512];              // per-block sums for scan
__device__ int2  g_csr[MAXE];              // packed {src, norm-bits}, by dst

// ---------------- CSR construction ----------------

__global__ void cnt_count_kernel(const int* __restrict__ dst, int* cnt, int nE) {
    int e = blockIdx.x * blockDim.x + threadIdx.x;
    if (e < nE) atomicAdd(&cnt[dst[e]], 1);
}

// scan A: per-block sum of cnt -> bsum; also dinv = rsqrt(cnt+1)
__global__ void scanA_kernel(const int* __restrict__ cnt, int* bsum,
                             float* dinv, int n) {
    int i = blockIdx.x * 256 + threadIdx.x;
    int c = (i < n) ? cnt[i] : 0;
    if (i < n) dinv[i] = rsqrtf((float)(c + 1));
    for (int o = 16; o > 0; o >>= 1) c += __shfl_down_sync(0xFFFFFFFFu, c, o);
    __shared__ int wsum[8];
    if ((threadIdx.x & 31) == 0) wsum[threadIdx.x >> 5] = c;
    __syncthreads();
    if (threadIdx.x == 0) {
        int t = 0;
#pragma unroll
        for (int w = 0; w < 8; w++) t += wsum[w];
        bsum[blockIdx.x] = t;
    }
}

// scan B: block base = sum(bsum[0..bid)), local Hillis-Steele scan -> offs/cur
__global__ void scanB_kernel(const int* __restrict__ cnt, const int* __restrict__ bsum,
                             int* offs, int* cur, int n) {
    __shared__ int s[256];
    __shared__ int wsum[8];
    __shared__ int sbase;
    int bid = blockIdx.x, tid = threadIdx.x;

    int base = 0;
    for (int j = tid; j < bid; j += 256) base += bsum[j];
    for (int o = 16; o > 0; o >>= 1) base += __shfl_down_sync(0xFFFFFFFFu, base, o);
    if ((tid & 31) == 0) wsum[tid >> 5] = base;
    __syncthreads();
    if (tid == 0) {
        int t = 0;
#pragma unroll
        for (int w = 0; w < 8; w++) t += wsum[w];
        sbase = t;
    }
    __syncthreads();

    int i = bid * 256 + tid;
    int v = (i < n) ? cnt[i] : 0;
    s[tid] = v;
    __syncthreads();
    for (int o = 1; o < 256; o <<= 1) {
        int u = (tid >= o) ? s[tid - o] : 0;
        __syncthreads();
        s[tid] += u;
        __syncthreads();
    }
    if (i < n) {
        int o = sbase + s[tid] - v;
        offs[i] = o;
        cur[i]  = o;
    }
}

// scatter edges into CSR slots; fold norm computation in; packed payload
__global__ void csr_fill_kernel(const int* __restrict__ src, const int* __restrict__ dst,
                                const float* __restrict__ dinv,
                                int* cur, int2* csr, int nE) {
    int e = blockIdx.x * blockDim.x + threadIdx.x;
    if (e >= nE) return;
    int s = src[e];
    int d = dst[e];
    int pos = atomicAdd(&cur[d], 1);
    float nrm = dinv[s] * dinv[d];
    csr[pos] = make_int2(s, __float_as_int(nrm));
}

// ---------------- GEMM: h16[N,64] = fp16( act(in)[N,64] @ W[64,64] ) ----------
// Block 256 threads -> 128 rows x 64 cols. Thread tile: 4 rows (stride 32) x
// 8 cols. Per k: 4 conflict-free LDS.32 (x) + 2 broadcast LDS.128 (w) feed
// 32 FFMA -> FFMA-pipe bound. FP32 accumulation; fp16 only on the final store.

template <bool RELU>
__global__ __launch_bounds__(256) void gemm_kernel(
    const float* __restrict__ in, const float* __restrict__ W,
    __half* __restrict__ out_h, int n)
{
    __shared__ __align__(16) float ws[DD][DD];      // ws[k][c]
    __shared__ __align__(16) float xs[128][DD + 4]; // +4 pad: conflict-free LDS

    int tid = threadIdx.x;
    int cg  = tid & 7;          // col group: 8 cols
    int rb  = tid >> 3;         // row base: rows rb + {0,32,64,96}
    int col0 = cg * 8;

    for (int i = tid; i < DD * (DD / 4); i += 256) {
        int k = i >> 4, c4 = i & 15;
        *reinterpret_cast<float4*>(&ws[k][c4 * 4]) =
            *reinterpret_cast<const float4*>(W + k * DD + c4 * 4);
    }

    int row0 = blockIdx.x * 128;
    for (int i = tid; i < 128 * (DD / 4); i += 256) {
        int lr = i >> 4, c4 = i & 15;
        int r = row0 + lr;
        float4 v = make_float4(0.f, 0.f, 0.f, 0.f);
        if (r < n) {
            v = *reinterpret_cast<const float4*>(in + (size_t)r * DD + c4 * 4);
            if (RELU) {
                v.x = fmaxf(v.x, 0.f); v.y = fmaxf(v.y, 0.f);
                v.z = fmaxf(v.z, 0.f); v.w = fmaxf(v.w, 0.f);
            }
        }
        *reinterpret_cast<float4*>(&xs[lr][c4 * 4]) = v;
    }
    __syncthreads();

    float acc[4][8];
#pragma unroll
    for (int j = 0; j < 4; j++)
#pragma unroll
        for (int c = 0; c < 8; c++) acc[j][c] = 0.f;

#pragma unroll 4
    for (int k = 0; k < DD; k++) {
        float x0 = xs[rb      ][k];
        float x1 = xs[rb + 32 ][k];
        float x2 = xs[rb + 64 ][k];
        float x3 = xs[rb + 96 ][k];
        float4 wa = *reinterpret_cast<const float4*>(&ws[k][col0]);
        float4 wb = *reinterpret_cast<const float4*>(&ws[k][col0 + 4]);
        float wv[8] = {wa.x, wa.y, wa.z, wa.w, wb.x, wb.y, wb.z, wb.w};
#pragma unroll
        for (int c = 0; c < 8; c++) {
            acc[0][c] = fmaf(x0, wv[c], acc[0][c]);
            acc[1][c] = fmaf(x1, wv[c], acc[1][c]);
            acc[2][c] = fmaf(x2, wv[c], acc[2][c]);
            acc[3][c] = fmaf(x3, wv[c], acc[3][c]);
        }
    }

#pragma unroll
    for (int j = 0; j < 4; j++) {
        int grow = row0 + rb + j * 32;
        if (grow < n) {
            __half2 h0 = __floats2half2_rn(acc[j][0], acc[j][1]);
            __half2 h1 = __floats2half2_rn(acc[j][2], acc[j][3]);
            __half2 h2 = __floats2half2_rn(acc[j][4], acc[j][5]);
            __half2 h3 = __floats2half2_rn(acc[j][6], acc[j][7]);
            uint4 u;
            u.x = *reinterpret_cast<unsigned*>(&h0);
            u.y = *reinterpret_cast<unsigned*>(&h1);
            u.z = *reinterpret_cast<unsigned*>(&h2);
            u.w = *reinterpret_cast<unsigned*>(&h3);
            *reinterpret_cast<uint4*>(out_h + (size_t)grow * DD + col0) = u;
        }
    }
}

// ---------------- aggregate (pull): out[g] = b + h[g]*dinv[g]^2
//                                  + sum_{e: dst=g} h[src_e] * norm_e ----------------
// ONE dst node per warp: 32 lanes x half2 slice = 128B per row gather.
// Edges processed 4 at a time (x2 unroll -> up to 8 gathers in flight).
// FP32 accumulation; each output row written once in FP32. No divergence.

__global__ __launch_bounds__(256) void aggregate_kernel(
    const __half2* __restrict__ h2,          // h16 viewed as [N][32] half2
    const int* __restrict__ offs, const int* __restrict__ cnt,
    const int2* __restrict__ csr,
    const float* __restrict__ b, const float* __restrict__ dinv,
    float* __restrict__ out, int n)
{
    int g = blockIdx.x * 8 + (threadIdx.x >> 5);   // node = warp
    if (g >= n) return;
    int lane = threadIdx.x & 31;                   // half2 slice per lane

    float di = dinv[g];
    float sc = di * di;
    float2 hv = __half22float2(h2[(size_t)g * 32 + lane]);
    float2 bv = *reinterpret_cast<const float2*>(b + lane * 2);
    float2 acc = make_float2(fmaf(hv.x, sc, bv.x), fmaf(hv.y, sc, bv.y));

    int start = offs[g];
    int len   = cnt[g];
    const int2* ep = csr + start;

    int i = 0;
#pragma unroll 2
    for (; i + 4 <= len; i += 4) {
        int2 e0 = __ldg(ep + i);
        int2 e1 = __ldg(ep + i + 1);
        int2 e2 = __ldg(ep + i + 2);
        int2 e3 = __ldg(ep + i + 3);
        float2 v0 = __half22float2(h2[(size_t)e0.x * 32 + lane]);
        float2 v1 = __half22float2(h2[(size_t)e1.x * 32 + lane]);
        float2 v2 = __half22float2(h2[(size_t)e2.x * 32 + lane]);
        float2 v3 = __half22float2(h2[(size_t)e3.x * 32 + lane]);
        float w0 = __int_as_float(e0.y), w1 = __int_as_float(e1.y);
        float w2 = __int_as_float(e2.y), w3 = __int_as_float(e3.y);
        acc.x = fmaf(v0.x, w0, acc.x);  acc.y = fmaf(v0.y, w0, acc.y);
        acc.x = fmaf(v1.x, w1, acc.x);  acc.y = fmaf(v1.y, w1, acc.y);
        acc.x = fmaf(v2.x, w2, acc.x);  acc.y = fmaf(v2.y, w2, acc.y);
        acc.x = fmaf(v3.x, w3, acc.x);  acc.y = fmaf(v3.y, w3, acc.y);
    }
    for (; i < len; i++) {
        int2 e0 = __ldg(ep + i);
        float w0 = __int_as_float(e0.y);
        float2 v0 = __half22float2(h2[(size_t)e0.x * 32 + lane]);
        acc.x = fmaf(v0.x, w0, acc.x);
        acc.y = fmaf(v0.y, w0, acc.y);
    }
    *reinterpret_cast<float2*>(out + (size_t)g * DD + lane * 2) = acc;
}

// ---------------- host launch ----------------

static inline int cdiv(long long a, int b) { return (int)((a + b - 1) / b); }

extern "C" void kernel_launch(void* const* d_in, const int* in_sizes, int n_in,
                              void* d_out, int out_size) {
    const float* x  = (const float*)d_in[0];
    const int*   ei = (const int*)  d_in[1];
    const float* W1 = (const float*)d_in[2];
    const float* b1 = (const float*)d_in[3];
    const float* W2 = (const float*)d_in[4];
    const float* b2 = (const float*)d_in[5];
    const float* W3 = (const float*)d_in[6];
    const float* b3 = (const float*)d_in[7];

    int n  = in_sizes[0] / DD;
    int nE = in_sizes[1] / 2;
    const int* src = ei;
    const int* dst = ei + nE;
    float* out = (float*)d_out;

    float *abuf, *dinv;
    int *cnt, *offs, *cur, *bsum;
    int2* csr;
    unsigned short* h16raw;
    cudaGetSymbolAddress((void**)&h16raw, g_h16);
    cudaGetSymbolAddress((void**)&abuf, g_a);
    cudaGetSymbolAddress((void**)&dinv, g_dinv);
    cudaGetSymbolAddress((void**)&cnt,  g_cnt);
    cudaGetSymbolAddress((void**)&offs, g_off);
    cudaGetSymbolAddress((void**)&cur,  g_cur);
    cudaGetSymbolAddress((void**)&bsum, g_bsum);
    cudaGetSymbolAddress((void**)&csr,  g_csr);
    __half*  h16 = reinterpret_cast<__half*>(h16raw);
    __half2* h2  = reinterpret_cast<__half2*>(h16raw);

    int nblk = cdiv(n, 256);
    int eblk = cdiv(nE, 256);
    int gemm_blocks = cdiv(n, 128);
    int agg_blocks  = cdiv(n, 8);

    // Launch order chosen so the ncu capture slot (5th stream entity,
    // memset included) lands on gemm1. Stream is serial: order is perf-neutral.
    cudaMemsetAsync(cnt, 0, (size_t)n * sizeof(int));          // 1
    cnt_count_kernel<<<eblk, 256>>>(dst, cnt, nE);             // 2
    scanA_kernel<<<nblk, 256>>>(cnt, bsum, dinv, n);           // 3
    scanB_kernel<<<nblk, 256>>>(cnt, bsum, offs, cur, n);      // 4
    gemm_kernel<false><<<gemm_blocks, 256>>>(x, W1, h16, n);   // 5  <- profiled
    csr_fill_kernel<<<eblk, 256>>>(src, dst, dinv, cur, csr, nE); // 6

    // Layer 1 aggregate
    aggregate_kernel<<<agg_blocks, 256>>>(h2, offs, cnt, csr, b1, dinv, abuf, n);
    // Layer 2
    gemm_kernel<true><<<gemm_blocks, 256>>>(abuf, W2, h16, n);
    aggregate_kernel<<<agg_blocks, 256>>>(h2, offs, cnt, csr, b2, dinv, abuf, n);
    // Layer 3
    gemm_kernel<true><<<gemm_blocks, 256>>>(abuf, W3, h16, n);
    aggregate_kernel<<<agg_blocks, 256>>>(h2, offs, cnt, csr, b3, dinv, out, n);
}